// round 1
// baseline (speedup 1.0000x reference)
#include <cuda_runtime.h>

#define TT 100   // sequence length
#define CC 16    // input embedding dim
#define HH 64    // head size
#define DD 256   // dense dim
#define RS 17    // padded row stride for [T,16] smem tiles (conflict-free column walk)

// wei gets 4 zero pad rows (rows 100..103) so the 8-row z tile needs no branch
#define WEI_ROWS 104

// Folded weights (computed by prologue kernels each call — deterministic)
__device__ float g_Wqc[CC * DD];
__device__ float g_Wkc[CC * DD];
__device__ float g_Wvc[CC * DD];
__device__ float g_M[CC * CC];

// ---------------------------------------------------------------------------
// Prologue 1: fold the chained projections. Wo[16,256] = W1[16,64] @ W2[64,256]
// One block per stream (q,k,v). 256 threads, one output column each.
// ---------------------------------------------------------------------------
__global__ void combine_kernel(const float* __restrict__ Wk, const float* __restrict__ Wq,
                               const float* __restrict__ Wv, const float* __restrict__ Wdk,
                               const float* __restrict__ Wdq, const float* __restrict__ Wdv) {
    const float* W1;
    const float* W2;
    float* Wo;
    if (blockIdx.x == 0)      { W1 = Wq; W2 = Wdq; Wo = g_Wqc; }
    else if (blockIdx.x == 1) { W1 = Wk; W2 = Wdk; Wo = g_Wkc; }
    else                      { W1 = Wv; W2 = Wdv; Wo = g_Wvc; }

    int d = threadIdx.x;  // 0..255
    float acc[CC];
#pragma unroll
    for (int c = 0; c < CC; c++) acc[c] = 0.f;

    for (int h = 0; h < HH; h++) {
        float w2 = W2[h * DD + d];  // coalesced
#pragma unroll
        for (int c = 0; c < CC; c++) acc[c] += __ldg(&W1[c * HH + h]) * w2;
    }
#pragma unroll
    for (int c = 0; c < CC; c++) Wo[c * DD + d] = acc[c];
}

// ---------------------------------------------------------------------------
// Prologue 2: M[16,16] = 0.25 * Wqc @ Wkc^T   (0.25 = C^-0.5, C=16)
// ---------------------------------------------------------------------------
__global__ void m_kernel() {
    int i = threadIdx.x;          // 0..255
    int c  = i >> 4;
    int c2 = i & 15;
    float s = 0.f;
    for (int d = 0; d < DD; d++) s += g_Wqc[c * DD + d] * g_Wkc[c2 * DD + d];
    g_M[c * CC + c2] = s * 0.25f;
}

// ---------------------------------------------------------------------------
// Main fused kernel: one CTA per batch element.
//   y   = x @ M                       [100,16]
//   wei = softmax(tril(y @ x^T))      [100,100]
//   z   = wei @ x                     [100,16]
//   out = z @ Wvc                     [100,256]
// ---------------------------------------------------------------------------
__global__ void __launch_bounds__(256, 2)
head_kernel(const float* __restrict__ x, float* __restrict__ out, int B) {
    extern __shared__ float sm[];
    float* xs  = sm;                               // TT*RS = 1700
    float* yz  = sm + TT * RS;                     // TT*RS = 1700 (y, then reused as z)
    float* wei = sm + 2 * TT * RS;                 // WEI_ROWS*TT = 10400
    float* Ms  = sm + 2 * TT * RS + WEI_ROWS * TT; // 256

    const int tid  = threadIdx.x;
    const int warp = tid >> 5;
    const int lane = tid & 31;
    const long long b = blockIdx.x;
    const float* xb = x + b * (long long)(TT * CC);

    // Load x tile (coalesced read, padded-stride store) + M
    for (int i = tid; i < TT * CC; i += 256)
        xs[(i >> 4) * RS + (i & 15)] = xb[i];
    if (tid < CC * CC) Ms[tid] = g_M[tid];
    // Zero pad rows of wei (rows 100..103)
    for (int i = tid; i < (WEI_ROWS - TT) * TT; i += 256)
        wei[TT * TT + i] = 0.f;
    __syncthreads();

    // ---- y = x @ M ----
    for (int i = tid; i < TT * CC; i += 256) {
        int t = i >> 4, j = i & 15;
        float a = 0.f;
#pragma unroll
        for (int c = 0; c < CC; c++) a += xs[t * RS + c] * Ms[c * CC + j];
        yz[t * RS + j] = a;
    }
    __syncthreads();

    // ---- logits: wei[t][s] = y[t]·x[s] (causal; zero above diagonal) ----
    // Each warp owns a group of 4 consecutive t rows; lanes stride over s.
    // y reads are warp-broadcast (cheap), xs reads are conflict-free (stride 17).
    for (int g = warp; g < 25; g += 8) {
        int t0 = g * 4;
        for (int s = lane; s < TT; s += 32) {
            float a0 = 0.f, a1 = 0.f, a2 = 0.f, a3 = 0.f;
            if (s <= t0 + 3) {
#pragma unroll
                for (int c = 0; c < CC; c++) {
                    float xv = xs[s * RS + c];
                    a0 += yz[(t0 + 0) * RS + c] * xv;
                    a1 += yz[(t0 + 1) * RS + c] * xv;
                    a2 += yz[(t0 + 2) * RS + c] * xv;
                    a3 += yz[(t0 + 3) * RS + c] * xv;
                }
            }
            wei[(t0 + 0) * TT + s] = (s <= t0 + 0) ? a0 : 0.f;
            wei[(t0 + 1) * TT + s] = (s <= t0 + 1) ? a1 : 0.f;
            wei[(t0 + 2) * TT + s] = (s <= t0 + 2) ? a2 : 0.f;
            wei[(t0 + 3) * TT + s] = (s <= t0 + 3) ? a3 : 0.f;
        }
    }
    __syncthreads();

    // ---- causal softmax, one warp per row ----
    for (int t = warp; t < TT; t += 8) {
        float m = -1e30f;
        for (int s = lane; s <= t; s += 32) m = fmaxf(m, wei[t * TT + s]);
#pragma unroll
        for (int o = 16; o; o >>= 1) m = fmaxf(m, __shfl_xor_sync(0xffffffffu, m, o));
        float sum = 0.f;
        for (int s = lane; s <= t; s += 32) {
            float e = __expf(wei[t * TT + s] - m);
            wei[t * TT + s] = e;
            sum += e;
        }
#pragma unroll
        for (int o = 16; o; o >>= 1) sum += __shfl_xor_sync(0xffffffffu, sum, o);
        float inv = 1.f / sum;
        for (int s = lane; s <= t; s += 32) wei[t * TT + s] *= inv;
    }
    __syncthreads();

    // ---- z = wei @ x  (overwrites yz) ----
    // Thread tile: 8 t-rows x 1 column. Upper-tri wei entries are 0, pad rows are 0,
    // so no inner branches needed.
    if (tid < 208) {  // 13 t-blocks * 16 columns
        int c  = tid & 15;
        int tb = tid >> 4;  // 0..12
        int smax = min(TT - 1, tb * 8 + 7);
        float a[8];
#pragma unroll
        for (int j = 0; j < 8; j++) a[j] = 0.f;
        for (int s = 0; s <= smax; s++) {
            float xv = xs[s * RS + c];
#pragma unroll
            for (int j = 0; j < 8; j++) a[j] += wei[(tb * 8 + j) * TT + s] * xv;
        }
#pragma unroll
        for (int j = 0; j < 8; j++) {
            int t = tb * 8 + j;
            if (t < TT) yz[t * RS + c] = a[j];
        }
    }
    __syncthreads();

    // ---- out = z @ Wvc ----
    // Thread owns 4 consecutive output columns; Wvc slice lives in 64 registers,
    // so the hot loop is pure FFMA + one broadcast LDS per c. Stores coalesced float4.
    {
        int d4 = tid & 63;   // column group 0..63
        int tc = tid >> 6;   // t-chunk 0..3 -> 25 rows each
        float4 w[CC];
#pragma unroll
        for (int c = 0; c < CC; c++)
            w[c] = *reinterpret_cast<const float4*>(&g_Wvc[c * DD + d4 * 4]);

        float* ob = out + b * (long long)(TT * DD);
        for (int t = tc * 25; t < tc * 25 + 25; t++) {
            float4 acc = make_float4(0.f, 0.f, 0.f, 0.f);
#pragma unroll
            for (int c = 0; c < CC; c++) {
                float zz = yz[t * RS + c];  // warp-uniform broadcast
                acc.x += zz * w[c].x;
                acc.y += zz * w[c].y;
                acc.z += zz * w[c].z;
                acc.w += zz * w[c].w;
            }
            *reinterpret_cast<float4*>(&ob[t * DD + d4 * 4]) = acc;
        }
    }
}

// ---------------------------------------------------------------------------
extern "C" void kernel_launch(void* const* d_in, const int* in_sizes, int n_in,
                              void* d_out, int out_size) {
    const float* x   = (const float*)d_in[0];
    const float* Wk  = (const float*)d_in[1];
    const float* Wq  = (const float*)d_in[2];
    const float* Wv  = (const float*)d_in[3];
    const float* Wdk = (const float*)d_in[4];
    const float* Wdq = (const float*)d_in[5];
    const float* Wdv = (const float*)d_in[6];
    float* out = (float*)d_out;

    int B = in_sizes[0] / (TT * CC);  // 4096

    const int smem_bytes = (2 * TT * RS + WEI_ROWS * TT + CC * CC) * (int)sizeof(float); // 56224
    cudaFuncSetAttribute(head_kernel, cudaFuncAttributeMaxDynamicSharedMemorySize, smem_bytes);

    combine_kernel<<<3, 256>>>(Wk, Wq, Wv, Wdk, Wdq, Wdv);
    m_kernel<<<1, 256>>>();
    head_kernel<<<B, 256, smem_bytes>>>(x, out, B);
}

// round 3
// speedup vs baseline: 1.8123x; 1.8123x over previous
#include <cuda_runtime.h>

#define TT 100   // sequence length
#define CC 16    // input embedding dim
#define HH 64    // head size
#define DD 256   // dense dim
#define RS 20    // padded row stride: float4-aligned, conflict-free LDS.128 column walk

// wei gets 4 zero pad rows (rows 100..103) so the 8-row z tile needs no branch
#define WEI_ROWS 104

// Folded weights (computed by prologue kernels each call — deterministic)
__device__ float g_Wqc[CC * DD];
__device__ float g_Wkc[CC * DD];
__device__ float g_Wvc[CC * DD];
__device__ float g_M[CC * CC];

// ---------------------------------------------------------------------------
// Prologue 1: fold chained projections. Wo[16,256] = W1[16,64] @ W2[64,256]
// One block per stream. W1 staged in smem; W2 reads coalesced + unrolled (MLP).
// ---------------------------------------------------------------------------
__global__ void combine_kernel(const float* __restrict__ Wk, const float* __restrict__ Wq,
                               const float* __restrict__ Wv, const float* __restrict__ Wdk,
                               const float* __restrict__ Wdq, const float* __restrict__ Wdv) {
    __shared__ float w1s[CC * HH];
    const float* W1;
    const float* W2;
    float* Wo;
    if (blockIdx.x == 0)      { W1 = Wq; W2 = Wdq; Wo = g_Wqc; }
    else if (blockIdx.x == 1) { W1 = Wk; W2 = Wdk; Wo = g_Wkc; }
    else                      { W1 = Wv; W2 = Wdv; Wo = g_Wvc; }

    int tid = threadIdx.x;
    for (int i = tid; i < CC * HH; i += 256) w1s[i] = W1[i];
    __syncthreads();

    int d = tid;  // 0..255, one output column
    float acc[CC];
#pragma unroll
    for (int c = 0; c < CC; c++) acc[c] = 0.f;

#pragma unroll 8
    for (int h = 0; h < HH; h++) {
        float w2 = W2[h * DD + d];  // coalesced; unroll-8 gives MLP=8
#pragma unroll
        for (int c = 0; c < CC; c++) acc[c] += w1s[c * HH + h] * w2;
    }
#pragma unroll
    for (int c = 0; c < CC; c++) Wo[c * DD + d] = acc[c];
}

// ---------------------------------------------------------------------------
// Prologue 2: M[16,16] = 0.25 * Wqc @ Wkc^T   (0.25 = C^-0.5, C=16)
// ---------------------------------------------------------------------------
__global__ void m_kernel() {
    int i = threadIdx.x;          // 0..255
    int c  = i >> 4;
    int c2 = i & 15;
    float s = 0.f;
#pragma unroll 8
    for (int d = 0; d < DD; d++) s += g_Wqc[c * DD + d] * g_Wkc[c2 * DD + d];
    g_M[c * CC + c2] = s * 0.25f;
}

// ---------------------------------------------------------------------------
// Main fused kernel: one CTA per batch element.
//   y   = x @ M                       [100,16]
//   wei = softmax(tril(y @ x^T))      [100,100]
//   z   = wei @ x                     [100,16]
//   out = z @ Wvc                     [100,256]
// ---------------------------------------------------------------------------
__global__ void __launch_bounds__(256, 2)
head_kernel(const float* __restrict__ x, float* __restrict__ out, int B) {
    extern __shared__ float sm[];
    float* xs  = sm;                               // TT*RS = 2000
    float* yz  = sm + TT * RS;                     // TT*RS = 2000 (y, then reused as z)
    float* wei = sm + 2 * TT * RS;                 // WEI_ROWS*TT = 10400
    float* Ms  = sm + 2 * TT * RS + WEI_ROWS * TT; // 256

    const int tid  = threadIdx.x;
    const int warp = tid >> 5;
    const int lane = tid & 31;
    const long long b = blockIdx.x;
    const float* xb = x + b * (long long)(TT * CC);

    // Load x tile (coalesced read, padded-stride store) + M
    for (int i = tid; i < TT * CC; i += 256)
        xs[(i >> 4) * RS + (i & 15)] = xb[i];
    if (tid < CC * CC) Ms[tid] = g_M[tid];
    // Zero pad rows of wei (rows 100..103)
    for (int i = tid; i < (WEI_ROWS - TT) * TT; i += 256)
        wei[TT * TT + i] = 0.f;
    __syncthreads();

    // ---- y = x @ M ----
    for (int i = tid; i < TT * CC; i += 256) {
        int t = i >> 4, j = i & 15;
        float a = 0.f;
#pragma unroll
        for (int c = 0; c < CC; c++) a += xs[t * RS + c] * Ms[c * CC + j];
        yz[t * RS + j] = a;
    }
    __syncthreads();

    // ---- logits: wei[t][s] = y[t]·x[s] (causal; zero above diagonal) ----
    // Warp owns 4 consecutive t rows; the 4 y-rows live in 64 registers.
    // xs row read as 4x LDS.128.
    for (int g = warp; g < 25; g += 8) {
        int t0 = g * 4;
        float4 yr[4][4];
#pragma unroll
        for (int j = 0; j < 4; j++)
#pragma unroll
            for (int q = 0; q < 4; q++)
                yr[j][q] = *reinterpret_cast<const float4*>(&yz[(t0 + j) * RS + q * 4]);

        for (int s = lane; s < TT; s += 32) {
            float a[4] = {0.f, 0.f, 0.f, 0.f};
            if (s <= t0 + 3) {
#pragma unroll
                for (int q = 0; q < 4; q++) {
                    float4 xv = *reinterpret_cast<const float4*>(&xs[s * RS + q * 4]);
#pragma unroll
                    for (int j = 0; j < 4; j++) {
                        a[j] += yr[j][q].x * xv.x;
                        a[j] += yr[j][q].y * xv.y;
                        a[j] += yr[j][q].z * xv.z;
                        a[j] += yr[j][q].w * xv.w;
                    }
                }
            }
#pragma unroll
            for (int j = 0; j < 4; j++)
                wei[(t0 + j) * TT + s] = (s <= t0 + j) ? a[j] : 0.f;
        }
    }
    __syncthreads();

    // ---- causal softmax, one warp per row ----
    for (int t = warp; t < TT; t += 8) {
        float m = -1e30f;
        for (int s = lane; s <= t; s += 32) m = fmaxf(m, wei[t * TT + s]);
#pragma unroll
        for (int o = 16; o; o >>= 1) m = fmaxf(m, __shfl_xor_sync(0xffffffffu, m, o));
        float sum = 0.f;
        for (int s = lane; s <= t; s += 32) {
            float e = __expf(wei[t * TT + s] - m);
            wei[t * TT + s] = e;
            sum += e;
        }
#pragma unroll
        for (int o = 16; o; o >>= 1) sum += __shfl_xor_sync(0xffffffffu, sum, o);
        float inv = 1.f / sum;
        for (int s = lane; s <= t; s += 32) wei[t * TT + s] *= inv;
    }
    __syncthreads();

    // ---- z = wei @ x  (overwrites yz) ----
    // Thread tile: 8 t-rows x 1 column; s in chunks of 4 with float4 wei reads.
    // scount clamped to TT: row stride is exactly TT, so reading past column
    // TT-1 would alias the NEXT row's entries (the R2 bug). min(.,TT)=100 is
    // still a multiple of 4; rows 100..103 then only ever touch zeroed pad rows.
    if (tid < 208) {  // 13 t-blocks * 16 columns
        int c  = tid & 15;
        int tb = tid >> 4;  // 0..12
        int scount = min(tb * 8 + 8, TT);  // multiple of 4
        float a[8];
#pragma unroll
        for (int j = 0; j < 8; j++) a[j] = 0.f;
        for (int s0 = 0; s0 < scount; s0 += 4) {
            float xv0 = xs[(s0 + 0) * RS + c];
            float xv1 = xs[(s0 + 1) * RS + c];
            float xv2 = xs[(s0 + 2) * RS + c];
            float xv3 = xs[(s0 + 3) * RS + c];
#pragma unroll
            for (int j = 0; j < 8; j++) {
                float4 w4 = *reinterpret_cast<const float4*>(&wei[(tb * 8 + j) * TT + s0]);
                a[j] += w4.x * xv0;
                a[j] += w4.y * xv1;
                a[j] += w4.z * xv2;
                a[j] += w4.w * xv3;
            }
        }
#pragma unroll
        for (int j = 0; j < 8; j++) {
            int t = tb * 8 + j;
            if (t < TT) yz[t * RS + c] = a[j];
        }
    }
    __syncthreads();

    // ---- out = z @ Wvc ----
    // Thread owns 4 consecutive output columns; Wvc slice in 64 registers.
    // z row read as 4x LDS.128 broadcast. Stores coalesced float4.
    {
        int d4 = tid & 63;   // column group 0..63
        int tc = tid >> 6;   // t-chunk 0..3 -> 25 rows each
        float4 w[CC];
#pragma unroll
        for (int c = 0; c < CC; c++)
            w[c] = *reinterpret_cast<const float4*>(&g_Wvc[c * DD + d4 * 4]);

        float* ob = out + b * (long long)(TT * DD);
        for (int t = tc * 25; t < tc * 25 + 25; t++) {
            float4 acc = make_float4(0.f, 0.f, 0.f, 0.f);
#pragma unroll
            for (int q = 0; q < 4; q++) {
                float4 zz = *reinterpret_cast<const float4*>(&yz[t * RS + q * 4]);
                acc.x += zz.x * w[q * 4 + 0].x;  acc.y += zz.x * w[q * 4 + 0].y;
                acc.z += zz.x * w[q * 4 + 0].z;  acc.w += zz.x * w[q * 4 + 0].w;
                acc.x += zz.y * w[q * 4 + 1].x;  acc.y += zz.y * w[q * 4 + 1].y;
                acc.z += zz.y * w[q * 4 + 1].z;  acc.w += zz.y * w[q * 4 + 1].w;
                acc.x += zz.z * w[q * 4 + 2].x;  acc.y += zz.z * w[q * 4 + 2].y;
                acc.z += zz.z * w[q * 4 + 2].z;  acc.w += zz.z * w[q * 4 + 2].w;
                acc.x += zz.w * w[q * 4 + 3].x;  acc.y += zz.w * w[q * 4 + 3].y;
                acc.z += zz.w * w[q * 4 + 3].z;  acc.w += zz.w * w[q * 4 + 3].w;
            }
            *reinterpret_cast<float4*>(&ob[t * DD + d4 * 4]) = acc;
        }
    }
}

// ---------------------------------------------------------------------------
extern "C" void kernel_launch(void* const* d_in, const int* in_sizes, int n_in,
                              void* d_out, int out_size) {
    const float* x   = (const float*)d_in[0];
    const float* Wk  = (const float*)d_in[1];
    const float* Wq  = (const float*)d_in[2];
    const float* Wv  = (const float*)d_in[3];
    const float* Wdk = (const float*)d_in[4];
    const float* Wdq = (const float*)d_in[5];
    const float* Wdv = (const float*)d_in[6];
    float* out = (float*)d_out;

    int B = in_sizes[0] / (TT * CC);  // 4096

    const int smem_bytes = (2 * TT * RS + WEI_ROWS * TT + CC * CC) * (int)sizeof(float); // 58624
    cudaFuncSetAttribute(head_kernel, cudaFuncAttributeMaxDynamicSharedMemorySize, smem_bytes);

    combine_kernel<<<3, 256>>>(Wk, Wq, Wv, Wdk, Wdq, Wdv);
    m_kernel<<<1, 256>>>();
    head_kernel<<<B, 256, smem_bytes>>>(x, out, B);
}

// round 4
// speedup vs baseline: 1.9669x; 1.0853x over previous
#include <cuda_runtime.h>

#define TT 100   // sequence length
#define CC 16    // input embedding dim
#define HH 64    // head size
#define DD 256   // dense dim
#define RS 20    // padded row stride: float4-aligned, conflict-free LDS.128 column walk

// wei gets 4 zero pad rows (rows 100..103) so the 8-row z tile needs no branch
#define WEI_ROWS 104

typedef unsigned long long ull;

// ---- packed fp32x2 helpers (sm_100+ PTX; .rn rounding = bit-identical to FFMA) ----
__device__ __forceinline__ ull ffma2(ull a, ull b, ull acc) {
    ull d;
    asm("fma.rn.f32x2 %0, %1, %2, %3;" : "=l"(d) : "l"(a), "l"(b), "l"(acc));
    return d;
}
__device__ __forceinline__ ull pack2(float lo, float hi) {
    ull r;
    asm("mov.b64 %0, {%1, %2};" : "=l"(r) : "f"(lo), "f"(hi));
    return r;
}
__device__ __forceinline__ float hadd2(ull v) {
    float lo, hi;
    asm("mov.b64 {%0, %1}, %2;" : "=f"(lo), "=f"(hi) : "l"(v));
    return lo + hi;
}

// Folded weights (computed by prologue kernels each call — deterministic)
__device__ float g_Wqc[CC * DD];
__device__ float g_Wkc[CC * DD];
__device__ float g_Wvc[CC * DD];
__device__ float g_M[CC * CC];

// ---------------------------------------------------------------------------
// Prologue 1: fold chained projections. Wo[16,256] = W1[16,64] @ W2[64,256]
// One block per stream. W2 column prefetched fully into registers (MLP ~55)
// so the DRAM latency is paid once, not 8 times.
// ---------------------------------------------------------------------------
__global__ void combine_kernel(const float* __restrict__ Wk, const float* __restrict__ Wq,
                               const float* __restrict__ Wv, const float* __restrict__ Wdk,
                               const float* __restrict__ Wdq, const float* __restrict__ Wdv) {
    __shared__ float w1s[CC * HH];
    const float* W1;
    const float* W2;
    float* Wo;
    if (blockIdx.x == 0)      { W1 = Wq; W2 = Wdq; Wo = g_Wqc; }
    else if (blockIdx.x == 1) { W1 = Wk; W2 = Wdk; Wo = g_Wkc; }
    else                      { W1 = Wv; W2 = Wdv; Wo = g_Wvc; }

    int tid = threadIdx.x;
    for (int i = tid; i < CC * HH; i += 256) w1s[i] = W1[i];
    __syncthreads();

    int d = tid;  // 0..255, one output column
    float w2r[HH];
#pragma unroll
    for (int h = 0; h < HH; h++) w2r[h] = W2[h * DD + d];  // all 64 loads in flight

#pragma unroll
    for (int c = 0; c < CC; c++) {
        float acc = 0.f;
#pragma unroll
        for (int h = 0; h < HH; h++) acc += w1s[c * HH + h] * w2r[h];
        Wo[c * DD + d] = acc;
    }
}

// ---------------------------------------------------------------------------
// Prologue 2: M[16,16] = 0.25 * Wqc @ Wkc^T   (0.25 = C^-0.5, C=16)
// float4 loads from L2-resident folded weights, unrolled for MLP.
// ---------------------------------------------------------------------------
__global__ void m_kernel() {
    int i = threadIdx.x;          // 0..255
    int c  = i >> 4;
    int c2 = i & 15;
    float s = 0.f;
#pragma unroll 8
    for (int d = 0; d < DD; d += 4) {
        float4 a = *reinterpret_cast<const float4*>(&g_Wqc[c * DD + d]);
        float4 b = *reinterpret_cast<const float4*>(&g_Wkc[c2 * DD + d]);
        s += a.x * b.x + a.y * b.y + a.z * b.z + a.w * b.w;
    }
    g_M[c * CC + c2] = s * 0.25f;
}

// ---------------------------------------------------------------------------
// Main fused kernel: one CTA per batch element.
//   y   = x @ M                       [100,16]
//   wei = softmax(tril(y @ x^T))      [100,100]
//   z   = wei @ x                     [100,16]
//   out = z @ Wvc                     [100,256]
// Hot loops use fma.rn.f32x2 packed along the contraction axis, so packed
// operands come straight from LDS.128 bit-reinterpretation (no pack movs).
// ---------------------------------------------------------------------------
__global__ void __launch_bounds__(256, 2)
head_kernel(const float* __restrict__ x, float* __restrict__ out, int B) {
    extern __shared__ float sm[];
    float* xs  = sm;                               // TT*RS = 2000 (base 16B-aligned)
    float* yz  = sm + TT * RS;                     // TT*RS = 2000 (8000B offset, 16B-aligned)
    float* wei = sm + 2 * TT * RS;                 // WEI_ROWS*TT = 10400 (16B-aligned)
    float* Ms  = sm + 2 * TT * RS + WEI_ROWS * TT; // 256

    const int tid  = threadIdx.x;
    const int warp = tid >> 5;
    const int lane = tid & 31;
    const long long b = blockIdx.x;
    const float* xb = x + b * (long long)(TT * CC);

    // Load x tile (coalesced read, padded-stride store) + M
    for (int i = tid; i < TT * CC; i += 256)
        xs[(i >> 4) * RS + (i & 15)] = xb[i];
    if (tid < CC * CC) Ms[tid] = g_M[tid];
    // Zero pad rows of wei (rows 100..103)
    for (int i = tid; i < (WEI_ROWS - TT) * TT; i += 256)
        wei[TT * TT + i] = 0.f;
    __syncthreads();

    // ---- y = x @ M ----
    for (int i = tid; i < TT * CC; i += 256) {
        int t = i >> 4, j = i & 15;
        float a = 0.f;
#pragma unroll
        for (int c = 0; c < CC; c++) a += xs[t * RS + c] * Ms[c * CC + j];
        yz[t * RS + j] = a;
    }
    __syncthreads();

    // ---- logits: wei[t][s] = y[t]·x[s] (causal; zero above diagonal) ----
    // Warp owns 4 consecutive t rows; y-rows live in registers as packed pairs.
    // Inner loop per s: 4x LDS.128 + 32 FFMA2 (vs 64 FFMA scalar).
    for (int g = warp; g < 25; g += 8) {
        int t0 = g * 4;
        ulonglong2 yr[4][4];
#pragma unroll
        for (int j = 0; j < 4; j++)
#pragma unroll
            for (int q = 0; q < 4; q++)
                yr[j][q] = *reinterpret_cast<const ulonglong2*>(&yz[(t0 + j) * RS + q * 4]);

        for (int s = lane; s < TT; s += 32) {
            ull a[4] = {0ull, 0ull, 0ull, 0ull};
            if (s <= t0 + 3) {
#pragma unroll
                for (int q = 0; q < 4; q++) {
                    ulonglong2 xv = *reinterpret_cast<const ulonglong2*>(&xs[s * RS + q * 4]);
#pragma unroll
                    for (int j = 0; j < 4; j++) {
                        a[j] = ffma2(yr[j][q].x, xv.x, a[j]);
                        a[j] = ffma2(yr[j][q].y, xv.y, a[j]);
                    }
                }
            }
#pragma unroll
            for (int j = 0; j < 4; j++)
                wei[(t0 + j) * TT + s] = (s <= t0 + j) ? hadd2(a[j]) : 0.f;
        }
    }
    __syncthreads();

    // ---- causal softmax, one warp per row ----
    for (int t = warp; t < TT; t += 8) {
        float m = -1e30f;
        for (int s = lane; s <= t; s += 32) m = fmaxf(m, wei[t * TT + s]);
#pragma unroll
        for (int o = 16; o; o >>= 1) m = fmaxf(m, __shfl_xor_sync(0xffffffffu, m, o));
        float sum = 0.f;
        for (int s = lane; s <= t; s += 32) {
            float e = __expf(wei[t * TT + s] - m);
            wei[t * TT + s] = e;
            sum += e;
        }
#pragma unroll
        for (int o = 16; o; o >>= 1) sum += __shfl_xor_sync(0xffffffffu, sum, o);
        float inv = 1.f / sum;
        for (int s = lane; s <= t; s += 32) wei[t * TT + s] *= inv;
    }
    __syncthreads();

    // ---- z = wei @ x  (overwrites yz) ----
    // Packed along s: wei float4 rows give natural (s,s+1) pairs; xv packed
    // once per chunk (2 movs) shared across all 8 t-rows.
    // scount clamped to TT (row stride == TT; past-end would alias next row).
    if (tid < 208) {  // 13 t-blocks * 16 columns
        int c  = tid & 15;
        int tb = tid >> 4;  // 0..12
        int scount = min(tb * 8 + 8, TT);  // multiple of 4
        ull a[8];
#pragma unroll
        for (int j = 0; j < 8; j++) a[j] = 0ull;
        for (int s0 = 0; s0 < scount; s0 += 4) {
            ull xp0 = pack2(xs[(s0 + 0) * RS + c], xs[(s0 + 1) * RS + c]);
            ull xp1 = pack2(xs[(s0 + 2) * RS + c], xs[(s0 + 3) * RS + c]);
#pragma unroll
            for (int j = 0; j < 8; j++) {
                ulonglong2 w4 = *reinterpret_cast<const ulonglong2*>(&wei[(tb * 8 + j) * TT + s0]);
                a[j] = ffma2(w4.x, xp0, a[j]);
                a[j] = ffma2(w4.y, xp1, a[j]);
            }
        }
#pragma unroll
        for (int j = 0; j < 8; j++) {
            int t = tb * 8 + j;
            if (t < TT) yz[t * RS + c] = hadd2(a[j]);
        }
    }
    __syncthreads();

    // ---- out = z @ Wvc ----
    // Wvc pre-packed along c into wp[c2][j] = (Wvc[2c2][d], Wvc[2c2+1][d])
    // (32 movs, once). Per t: 4 LDS.128 (z-pairs) + 32 FFMA2 + 4 hadd + STG.128.
    {
        int d4 = tid & 63;   // column group 0..63
        int tc = tid >> 6;   // t-chunk 0..3 -> 25 rows each
        ull wp[8][4];
#pragma unroll
        for (int c2 = 0; c2 < 8; c2++) {
            float4 w0 = *reinterpret_cast<const float4*>(&g_Wvc[(2 * c2 + 0) * DD + d4 * 4]);
            float4 w1 = *reinterpret_cast<const float4*>(&g_Wvc[(2 * c2 + 1) * DD + d4 * 4]);
            wp[c2][0] = pack2(w0.x, w1.x);
            wp[c2][1] = pack2(w0.y, w1.y);
            wp[c2][2] = pack2(w0.z, w1.z);
            wp[c2][3] = pack2(w0.w, w1.w);
        }

        float* ob = out + b * (long long)(TT * DD);
        for (int t = tc * 25; t < tc * 25 + 25; t++) {
            ull acc[4] = {0ull, 0ull, 0ull, 0ull};
#pragma unroll
            for (int q = 0; q < 4; q++) {
                ulonglong2 zp = *reinterpret_cast<const ulonglong2*>(&yz[t * RS + q * 4]);
#pragma unroll
                for (int j = 0; j < 4; j++) {
                    acc[j] = ffma2(zp.x, wp[2 * q + 0][j], acc[j]);
                    acc[j] = ffma2(zp.y, wp[2 * q + 1][j], acc[j]);
                }
            }
            float4 o4;
            o4.x = hadd2(acc[0]);
            o4.y = hadd2(acc[1]);
            o4.z = hadd2(acc[2]);
            o4.w = hadd2(acc[3]);
            *reinterpret_cast<float4*>(&ob[t * DD + d4 * 4]) = o4;
        }
    }
}

// ---------------------------------------------------------------------------
extern "C" void kernel_launch(void* const* d_in, const int* in_sizes, int n_in,
                              void* d_out, int out_size) {
    const float* x   = (const float*)d_in[0];
    const float* Wk  = (const float*)d_in[1];
    const float* Wq  = (const float*)d_in[2];
    const float* Wv  = (const float*)d_in[3];
    const float* Wdk = (const float*)d_in[4];
    const float* Wdq = (const float*)d_in[5];
    const float* Wdv = (const float*)d_in[6];
    float* out = (float*)d_out;

    int B = in_sizes[0] / (TT * CC);  // 4096

    const int smem_bytes = (2 * TT * RS + WEI_ROWS * TT + CC * CC) * (int)sizeof(float); // 58624
    cudaFuncSetAttribute(head_kernel, cudaFuncAttributeMaxDynamicSharedMemorySize, smem_bytes);

    combine_kernel<<<3, 256>>>(Wk, Wq, Wv, Wdk, Wdq, Wdv);
    m_kernel<<<1, 256>>>();
    head_kernel<<<B, 256, smem_bytes>>>(x, out, B);
}